// round 7
// baseline (speedup 1.0000x reference)
#include <cuda_runtime.h>
#include <cstdint>

// RecallLoss: input [N=8, C=21, H=512, W=512] f32, target [N,H,W] int64/int32
// (auto-detected). loss = 1 - mean_{n,c} (tp+eps)/(tt+eps).
//
// R7: smem-staged streaming. 148 persistent blocks double-buffer 84KB tiles
// (21 ch x 4KB) via cp.async.cg so DRAM sees channel-major contiguous 4KB
// reads (row-buffer friendly) and 84KB/SM stays in flight independent of
// register pressure. Prior rounds proved neither occupancy nor atomics could
// push DRAM past ~65% with 21 x 1MB-strided per-thread streams.

#define SMOOTH 1e-5f

constexpr int N_IMG  = 8;
constexpr int C_CLS  = 21;
constexpr int HW     = 512 * 512;          // 262144 positions per image
constexpr int NC     = N_IMG * C_CLS;      // 168 bins
constexpr int TPB    = 256;
constexpr int NWARP  = TPB / 32;           // 8

constexpr int TILE_POS   = 1024;                  // positions per tile
constexpr int CH_FLOATS  = TILE_POS;              // 4KB per channel
constexpr int TILE_FLTS  = C_CLS * CH_FLOATS;     // 21504 floats = 84KB
constexpr int TILE_BYTES = TILE_FLTS * 4;         // 86016
constexpr int NTILES     = N_IMG * HW / TILE_POS; // 2048
constexpr int TILES_PER_IMG = HW / TILE_POS;      // 256
constexpr int GRIDX  = 148;                       // persistent, 1 block/SM

__device__ int g_tp[NC];
__device__ int g_tt[NC];
__device__ unsigned int g_arrive;

__device__ __forceinline__ unsigned smem_u32(const void* p) {
    return (unsigned)__cvta_generic_to_shared(p);
}
__device__ __forceinline__ void cp_async16(void* dst_smem, const void* src) {
    asm volatile("cp.async.cg.shared.global [%0], [%1], 16;"
                 :: "r"(smem_u32(dst_smem)), "l"(src) : "memory");
}
__device__ __forceinline__ void cp_commit() {
    asm volatile("cp.async.commit_group;" ::: "memory");
}
template <int N>
__device__ __forceinline__ void cp_wait() {
    asm volatile("cp.async.wait_group %0;" :: "n"(N) : "memory");
}

// Warp-aggregated count: leaders of distinct classes touch distinct banks of
// the warp-private row, so one plain LDS+IADD+STS per call replaces atomics.
__device__ __forceinline__ void warp_count(
    unsigned int* __restrict__ cnt, int bin, int pred_match, int lid)
{
    unsigned int grp = __match_any_sync(0xffffffffu, bin);
    unsigned int mb  = __ballot_sync(0xffffffffu, pred_match);
    unsigned int add = __popc(grp) + (__popc(grp & mb) << 16);
    if ((grp & ((1u << lid) - 1u)) == 0u)
        cnt[bin] += add;
}

// Stage one tile: iteration j loads channel j's 4KB contiguously
// (thread tid -> 16B at offset tid*16). Block-wide contiguous per channel.
__device__ __forceinline__ void stage_tile(
    float* __restrict__ buf, const float* __restrict__ inp, int t, int tid)
{
    const int n    = t >> 8;                       // TILES_PER_IMG = 256
    const int pos0 = (t & (TILES_PER_IMG - 1)) << 10;
    const float* src = inp + n * C_CLS * HW + pos0 + tid * 4;
    float* dst = buf + tid * 4;
    #pragma unroll
    for (int j = 0; j < C_CLS; j++) {
        cp_async16(dst + j * CH_FLOATS, src + j * HW);
    }
}

__global__ __launch_bounds__(TPB, 1) void recall_fused_kernel(
    const float* __restrict__ inp, const void* __restrict__ tgt_raw,
    float* __restrict__ out)
{
    extern __shared__ float dynbuf[];              // 2 x TILE_FLTS
    __shared__ unsigned int s_cnt[NWARP][NC];      // packed tp<<16 | tt
    __shared__ int s_is64;
    __shared__ float s_red[NWARP];

    const int tid = threadIdx.x;
    const int wid = tid >> 5;
    const int lid = tid & 31;
    for (int k = lid; k < NC; k += 32) s_cnt[wid][k] = 0;

    // dtype detect: int64 targets in [0,21) have all-zero odd 32-bit words.
    if (tid == 0) {
        const int* w = (const int*)tgt_raw;
        int is64 = 1;
        #pragma unroll
        for (int k = 0; k < 16; k++) is64 &= (w[2 * k + 1] == 0);
        s_is64 = is64;
    }
    __syncthreads();
    const int is64 = s_is64;

    const int bid = blockIdx.x;
    const int nt  = (NTILES - bid + GRIDX - 1) / GRIDX;  // 13 or 14 tiles

    // Prologue: stage tile 0 into buffer 0.
    stage_tile(dynbuf, inp, bid, tid);
    cp_commit();

    unsigned int* const cnt = s_cnt[wid];

    #pragma unroll 1
    for (int k = 0; k < nt; k++) {
        const int t    = bid + k * GRIDX;
        const bool more = (k + 1 < nt);
        if (more) {
            stage_tile(dynbuf + ((k + 1) & 1) * TILE_FLTS, inp,
                       bid + (k + 1) * GRIDX, tid);
            cp_commit();
        }

        // Target loads (independent of smem) issued before the wait so their
        // DRAM latency overlaps the staging wait.
        const int n   = t >> 8;
        const int pos = ((t & (TILES_PER_IMG - 1)) << 10) + tid * 4;
        int t0, t1, t2, t3;
        if (is64) {
            const long long* tp = (const long long*)tgt_raw + (n * HW + pos);
            longlong2 a = __ldcs(reinterpret_cast<const longlong2*>(tp));
            longlong2 b = __ldcs(reinterpret_cast<const longlong2*>(tp + 2));
            t0 = (int)a.x; t1 = (int)a.y; t2 = (int)b.x; t3 = (int)b.y;
        } else {
            const int* tp = (const int*)tgt_raw + (n * HW + pos);
            int4 a = __ldcs(reinterpret_cast<const int4*>(tp));
            t0 = a.x; t1 = a.y; t2 = a.z; t3 = a.w;
        }

        if (more) cp_wait<1>(); else cp_wait<0>();
        __syncthreads();                            // tile (k) visible to all

        const float* B = dynbuf + (k & 1) * TILE_FLTS + tid * 4;

        // Channel 0 seeds; strict > keeps first max index (jnp.argmax ties).
        float4 v = *reinterpret_cast<const float4*>(B);
        float m0 = v.x, m1 = v.y, m2 = v.z, m3 = v.w;
        int   i0 = 0,  i1 = 0,  i2 = 0,  i3 = 0;
        #pragma unroll
        for (int c = 1; c < C_CLS; c++) {
            float4 u = *reinterpret_cast<const float4*>(B + c * CH_FLOATS);
            if (u.x > m0) { m0 = u.x; i0 = c; }
            if (u.y > m1) { m1 = u.y; i1 = c; }
            if (u.z > m2) { m2 = u.z; i2 = c; }
            if (u.w > m3) { m3 = u.w; i3 = c; }
        }

        const int nb = n * C_CLS;
        warp_count(cnt, nb + t0, i0 == t0, lid);
        warp_count(cnt, nb + t1, i1 == t1, lid);
        warp_count(cnt, nb + t2, i2 == t2, lid);
        warp_count(cnt, nb + t3, i3 == t3, lid);

        __syncthreads();   // all reads of buf(k&1) done before iter k+1
                           // restages into it
    }

    // Block reduce: 168 bins, sum 8 warp rows, one global atomic pair each.
    if (tid < NC) {
        unsigned int a = 0;
        #pragma unroll
        for (int w = 0; w < NWARP; w++) a += s_cnt[w][tid];
        atomicAdd(&g_tt[tid], (int)(a & 0xFFFFu));
        atomicAdd(&g_tp[tid], (int)(a >> 16));
    }

    // ---- last-block epilogue -------------------------------------------
    __shared__ int s_last;
    __threadfence();
    if (tid == 0) {
        unsigned int old = atomicAdd(&g_arrive, 1u);
        s_last = (old == (unsigned int)(GRIDX - 1));
    }
    __syncthreads();
    if (!s_last) return;

    __threadfence();
    float r = 0.0f;
    if (tid < NC) {
        r = ((float)g_tp[tid] + SMOOTH) / ((float)g_tt[tid] + SMOOTH);
    }
    #pragma unroll
    for (int o = 16; o > 0; o >>= 1) r += __shfl_down_sync(0xffffffffu, r, o);
    if (lid == 0) s_red[wid] = r;
    __syncthreads();
    if (tid == 0) {
        float s = 0.0f;
        #pragma unroll
        for (int w = 0; w < NWARP; w++) s += s_red[w];
        out[0] = 1.0f - s / (float)NC;
    }

    // Reset state for the next graph replay.
    if (tid < NC) { g_tp[tid] = 0; g_tt[tid] = 0; }
    if (tid == 0) g_arrive = 0u;
}

extern "C" void kernel_launch(void* const* d_in, const int* in_sizes, int n_in,
                              void* d_out, int out_size) {
    const float* inp = (const float*)d_in[0];
    const void*  tgt = d_in[1];
    float* out = (float*)d_out;

    static bool attr_set = false;   // host-side idempotent attribute, not state
    cudaFuncSetAttribute(recall_fused_kernel,
                         cudaFuncAttributeMaxDynamicSharedMemorySize,
                         2 * TILE_BYTES);
    (void)attr_set;

    recall_fused_kernel<<<GRIDX, TPB, 2 * TILE_BYTES>>>(inp, tgt, out);
}

// round 9
// speedup vs baseline: 1.0030x; 1.0030x over previous
#include <cuda_runtime.h>
#include <cstdint>

// RecallLoss: input [N=8, C=21, H=512, W=512] f32, target [N,H,W] int64/int32
// (auto-detected). loss = 1 - mean_{n,c} (tp+eps)/(tt+eps).
//
// Smem-staged streaming: 148 persistent blocks double-buffer 84KB tiles
// (21 ch x 4KB) via cp.async.cg so DRAM sees channel-major contiguous 4KB
// reads (row-buffer friendly) and 84KB/SM stays in flight independent of
// register pressure. Rounds 3-6 proved neither occupancy nor atomics could
// push DRAM past ~65% with 21 x 1MB-strided per-thread streams.

#define SMOOTH 1e-5f

constexpr int N_IMG  = 8;
constexpr int C_CLS  = 21;
constexpr int HW     = 512 * 512;          // 262144 positions per image
constexpr int NC     = N_IMG * C_CLS;      // 168 bins
constexpr int TPB    = 256;
constexpr int NWARP  = TPB / 32;           // 8

constexpr int TILE_POS   = 1024;                  // positions per tile
constexpr int CH_FLOATS  = TILE_POS;              // 4KB per channel
constexpr int TILE_FLTS  = C_CLS * CH_FLOATS;     // 21504 floats = 84KB
constexpr int TILE_BYTES = TILE_FLTS * 4;         // 86016
constexpr int NTILES     = N_IMG * HW / TILE_POS; // 2048
constexpr int TILES_PER_IMG = HW / TILE_POS;      // 256
constexpr int GRIDX  = 148;                       // persistent, 1 block/SM

__device__ int g_tp[NC];
__device__ int g_tt[NC];
__device__ unsigned int g_arrive;

__device__ __forceinline__ unsigned smem_u32(const void* p) {
    return (unsigned)__cvta_generic_to_shared(p);
}
__device__ __forceinline__ void cp_async16(void* dst_smem, const void* src) {
    asm volatile("cp.async.cg.shared.global [%0], [%1], 16;"
                 :: "r"(smem_u32(dst_smem)), "l"(src) : "memory");
}
__device__ __forceinline__ void cp_commit() {
    asm volatile("cp.async.commit_group;" ::: "memory");
}
template <int N>
__device__ __forceinline__ void cp_wait() {
    asm volatile("cp.async.wait_group %0;" :: "n"(N) : "memory");
}

// Warp-aggregated count: leaders of distinct classes touch distinct words of
// the warp-private row, so one plain LDS+IADD+STS per call replaces atomics.
__device__ __forceinline__ void warp_count(
    unsigned int* __restrict__ cnt, int bin, int pred_match, int lid)
{
    unsigned int grp = __match_any_sync(0xffffffffu, bin);
    unsigned int mb  = __ballot_sync(0xffffffffu, pred_match);
    unsigned int add = __popc(grp) + (__popc(grp & mb) << 16);
    if ((grp & ((1u << lid) - 1u)) == 0u)
        cnt[bin] += add;
}

// Stage one tile: iteration j loads channel j's 4KB contiguously
// (thread tid -> 16B at offset tid*16). Block-wide contiguous per channel.
__device__ __forceinline__ void stage_tile(
    float* __restrict__ buf, const float* __restrict__ inp, int t, int tid)
{
    const int n    = t >> 8;                       // TILES_PER_IMG = 256
    const int pos0 = (t & (TILES_PER_IMG - 1)) << 10;
    const float* src = inp + n * C_CLS * HW + pos0 + tid * 4;
    float* dst = buf + tid * 4;
    #pragma unroll
    for (int j = 0; j < C_CLS; j++) {
        cp_async16(dst + j * CH_FLOATS, src + j * HW);
    }
}

__global__ __launch_bounds__(TPB, 1) void recall_fused_kernel(
    const float* __restrict__ inp, const void* __restrict__ tgt_raw,
    float* __restrict__ out)
{
    extern __shared__ float dynbuf[];              // 2 x TILE_FLTS
    __shared__ unsigned int s_cnt[NWARP][NC];      // packed tp<<16 | tt
    __shared__ int s_is64;
    __shared__ float s_red[NWARP];

    const int tid = threadIdx.x;
    const int wid = tid >> 5;
    const int lid = tid & 31;
    for (int k = lid; k < NC; k += 32) s_cnt[wid][k] = 0;

    // dtype detect: int64 targets in [0,21) have all-zero odd 32-bit words;
    // for int32 the chance 16 specific odd words are all 0 is (1/21)^16 ~ 0.
    if (tid == 0) {
        const int* w = (const int*)tgt_raw;
        int is64 = 1;
        #pragma unroll
        for (int k = 0; k < 16; k++) is64 &= (w[2 * k + 1] == 0);
        s_is64 = is64;
    }
    __syncthreads();
    const int is64 = s_is64;

    const int bid = blockIdx.x;
    const int nt  = (NTILES - bid + GRIDX - 1) / GRIDX;  // 13 or 14 tiles

    // Prologue: stage tile 0 into buffer 0.
    stage_tile(dynbuf, inp, bid, tid);
    cp_commit();

    unsigned int* const cnt = s_cnt[wid];

    #pragma unroll 1
    for (int k = 0; k < nt; k++) {
        const int t     = bid + k * GRIDX;
        const bool more = (k + 1 < nt);
        if (more) {
            stage_tile(dynbuf + ((k + 1) & 1) * TILE_FLTS, inp,
                       bid + (k + 1) * GRIDX, tid);
            cp_commit();
        }

        // Target loads (independent of smem) issued before the wait so their
        // DRAM latency overlaps the staging wait.
        const int n   = t >> 8;
        const int pos = ((t & (TILES_PER_IMG - 1)) << 10) + tid * 4;
        int t0, t1, t2, t3;
        if (is64) {
            const long long* tp = (const long long*)tgt_raw + (n * HW + pos);
            longlong2 a = __ldcs(reinterpret_cast<const longlong2*>(tp));
            longlong2 b = __ldcs(reinterpret_cast<const longlong2*>(tp + 2));
            t0 = (int)a.x; t1 = (int)a.y; t2 = (int)b.x; t3 = (int)b.y;
        } else {
            const int* tp = (const int*)tgt_raw + (n * HW + pos);
            int4 a = __ldcs(reinterpret_cast<const int4*>(tp));
            t0 = a.x; t1 = a.y; t2 = a.z; t3 = a.w;
        }

        if (more) cp_wait<1>(); else cp_wait<0>();
        __syncthreads();                            // tile k visible to all

        const float* B = dynbuf + (k & 1) * TILE_FLTS + tid * 4;

        // Channel 0 seeds; strict > keeps first max index (jnp.argmax ties).
        float4 v = *reinterpret_cast<const float4*>(B);
        float m0 = v.x, m1 = v.y, m2 = v.z, m3 = v.w;
        int   i0 = 0,  i1 = 0,  i2 = 0,  i3 = 0;
        #pragma unroll
        for (int c = 1; c < C_CLS; c++) {
            float4 u = *reinterpret_cast<const float4*>(B + c * CH_FLOATS);
            if (u.x > m0) { m0 = u.x; i0 = c; }
            if (u.y > m1) { m1 = u.y; i1 = c; }
            if (u.z > m2) { m2 = u.z; i2 = c; }
            if (u.w > m3) { m3 = u.w; i3 = c; }
        }

        const int nb = n * C_CLS;
        warp_count(cnt, nb + t0, i0 == t0, lid);
        warp_count(cnt, nb + t1, i1 == t1, lid);
        warp_count(cnt, nb + t2, i2 == t2, lid);
        warp_count(cnt, nb + t3, i3 == t3, lid);

        __syncthreads();   // all reads of buf(k&1) done before iter k+1
                           // restages into it
    }

    // Block reduce: 168 bins, sum 8 warp rows, one global atomic pair each.
    if (tid < NC) {
        unsigned int a = 0;
        #pragma unroll
        for (int w = 0; w < NWARP; w++) a += s_cnt[w][tid];
        atomicAdd(&g_tt[tid], (int)(a & 0xFFFFu));
        atomicAdd(&g_tp[tid], (int)(a >> 16));
    }

    // ---- last-block epilogue -------------------------------------------
    __shared__ int s_last;
    __threadfence();   // release this block's counter contributions
    if (tid == 0) {
        unsigned int old = atomicAdd(&g_arrive, 1u);
        s_last = (old == (unsigned int)(GRIDX - 1));
    }
    __syncthreads();
    if (!s_last) return;

    __threadfence();   // acquire all blocks' contributions
    float r = 0.0f;
    if (tid < NC) {
        r = ((float)g_tp[tid] + SMOOTH) / ((float)g_tt[tid] + SMOOTH);
    }
    #pragma unroll
    for (int o = 16; o > 0; o >>= 1) r += __shfl_down_sync(0xffffffffu, r, o);
    if (lid == 0) s_red[wid] = r;
    __syncthreads();
    if (tid == 0) {
        float s = 0.0f;
        #pragma unroll
        for (int w = 0; w < NWARP; w++) s += s_red[w];
        out[0] = 1.0f - s / (float)NC;
    }

    // Reset state for the next graph replay.
    if (tid < NC) { g_tp[tid] = 0; g_tt[tid] = 0; }
    if (tid == 0) g_arrive = 0u;
}

extern "C" void kernel_launch(void* const* d_in, const int* in_sizes, int n_in,
                              void* d_out, int out_size) {
    const float* inp = (const float*)d_in[0];
    const void*  tgt = d_in[1];
    float* out = (float*)d_out;

    // Sticky function attribute; deterministic, capture-safe (no stream work).
    cudaFuncSetAttribute(recall_fused_kernel,
                         cudaFuncAttributeMaxDynamicSharedMemorySize,
                         2 * TILE_BYTES);

    recall_fused_kernel<<<GRIDX, TPB, 2 * TILE_BYTES>>>(inp, tgt, out);
}